// round 4
// baseline (speedup 1.0000x reference)
#include <cuda_runtime.h>

#define NB 16
#define NN 4096
#define NE 131072
#define NH 16
#define NT 3
#define NFC 20
#define BHD 256                     // B*H = 256 floats per node row
#define INV_SQRT_DEG 0.17677669529663687f   // 1/sqrt(E/N) = 1/sqrt(32)

#define KSPLIT 16                   // j-reduction splits in k_gemm
#define GROWS 256                   // rows per gemm block
#define KJ 32                       // j-chunk per smem stage
#define WPITCH 34                   // Ws smem pitch (34 mod 32 == 2 -> LDS.64 conflict-free)

// ---------------- device scratch (static: no allocs allowed) ----------------
__device__ __align__(16) float g_h0[NN * BHD];     // 4 MB ping
__device__ __align__(16) float g_h1[NN * BHD];     // 4 MB pong
__device__ __align__(16) float g_A[NN * 48];       // a[i][b*3+p]
__device__ __align__(16) float g_C[NN * 48];       // c[j][b*3+q]
__device__ __align__(16) float g_R[KSPLIT * NN * 48];   // partial R = W2 @ C
__device__ int   g_cnt[NN];
__device__ int   g_rowptr[NN + 1];
__device__ int   g_cursor[NN];
__device__ int   g_csr[NE];                        // src | (type<<16), sorted by dst
__device__ float g_ew[2 * NT];                     // per-layer per-type edge weight
__device__ float g_invF[NB * 9];

// ---------------- f32x2 packed-FMA helpers ----------------
__device__ __forceinline__ unsigned long long pk2(float lo, float hi) {
    unsigned long long r;
    asm("mov.b64 %0, {%1, %2};" : "=l"(r) : "f"(lo), "f"(hi));
    return r;
}
__device__ __forceinline__ void upk2(unsigned long long v, float& lo, float& hi) {
    asm("mov.b64 {%0, %1}, %2;" : "=f"(lo), "=f"(hi) : "l"(v));
}
__device__ __forceinline__ void fma2(unsigned long long& d, unsigned long long a,
                                     unsigned long long b) {
    asm("fma.rn.f32x2 %0, %1, %2, %0;" : "+l"(d) : "l"(a), "l"(b));
}

// ---------------- init: zero counters, edge weights, inv(F) ----------------
__global__ void k_init(const float* __restrict__ F,
                       const float* __restrict__ fc10, const float* __restrict__ fc20,
                       const float* __restrict__ fc11, const float* __restrict__ fc21) {
    int tid = threadIdx.x;
    for (int i = tid; i < NN; i += 256) g_cnt[i] = 0;
    if (tid < 6) {
        int l = tid / 3, t = tid % 3;
        const float* f1 = l ? fc11 : fc10;
        const float* f2 = l ? fc21 : fc20;
        float s = 0.f;
        #pragma unroll
        for (int f = 0; f < NFC; f++) s = fmaf(fmaxf(f1[t * NFC + f], 0.f), f2[f], s);
        g_ew[tid] = s;
    }
    if (tid >= 32 && tid < 32 + NB) {
        int b = tid - 32;
        const float* m = F + b * 9;
        float a00=m[0],a01=m[1],a02=m[2],a10=m[3],a11=m[4],a12=m[5],a20=m[6],a21=m[7],a22=m[8];
        float det = a00*(a11*a22-a12*a21) - a01*(a10*a22-a12*a20) + a02*(a10*a21-a11*a20);
        float id = 1.f / det;
        float* o = g_invF + b * 9;
        o[0]=(a11*a22-a12*a21)*id; o[1]=(a02*a21-a01*a22)*id; o[2]=(a01*a12-a02*a11)*id;
        o[3]=(a12*a20-a10*a22)*id; o[4]=(a00*a22-a02*a20)*id; o[5]=(a02*a10-a00*a12)*id;
        o[6]=(a10*a21-a11*a20)*id; o[7]=(a01*a20-a00*a21)*id; o[8]=(a00*a11-a01*a10)*id;
    }
}

// ---------------- CSR build ----------------
__global__ void k_hist(const int* __restrict__ edge_dst) {
    int e = blockIdx.x * 256 + threadIdx.x;
    if (e < NE) atomicAdd(&g_cnt[edge_dst[e]], 1);
}

__global__ void k_scan() {   // 1 block, 1024 threads, 4 items/thread
    int tid = threadIdx.x;
    int v[4]; int s = 0;
    #pragma unroll
    for (int j = 0; j < 4; j++) { v[j] = g_cnt[tid * 4 + j]; s += v[j]; }
    int lane = tid & 31, wid = tid >> 5;
    const unsigned full = 0xFFFFFFFFu;
    int x = s;
    #pragma unroll
    for (int off = 1; off < 32; off <<= 1) { int y = __shfl_up_sync(full, x, off); if (lane >= off) x += y; }
    __shared__ int swarp[32];
    if (lane == 31) swarp[wid] = x;
    __syncthreads();
    if (wid == 0) {
        int y = swarp[lane];
        #pragma unroll
        for (int off = 1; off < 32; off <<= 1) { int z = __shfl_up_sync(full, y, off); if (lane >= off) y += z; }
        swarp[lane] = y;
    }
    __syncthreads();
    int base = (x - s) + (wid > 0 ? swarp[wid - 1] : 0);
    int run = base;
    #pragma unroll
    for (int j = 0; j < 4; j++) {
        g_rowptr[tid * 4 + j] = run;
        g_cursor[tid * 4 + j] = run;
        run += v[j];
    }
    if (tid == 1023) g_rowptr[NN] = run;
}

__global__ void k_scatter(const int* __restrict__ edge_src,
                          const int* __restrict__ edge_dst,
                          const int* __restrict__ edge_type) {
    int e = blockIdx.x * 256 + threadIdx.x;
    if (e < NE) {
        int pos = atomicAdd(&g_cursor[edge_dst[e]], 1);
        g_csr[pos] = edge_src[e] | (edge_type[e] << 16);
    }
}

// ---------------- h0 = (F @ pos) @ W_in ----------------
__global__ void k_h0(const float* __restrict__ F, const float* __restrict__ node_pos,
                     const float* __restrict__ W_in) {
    int n = blockIdx.x, tid = threadIdx.x;
    int b = tid >> 4, k = tid & 15;
    __shared__ float sp[3];
    if (tid < 3) sp[tid] = node_pos[n * 3 + tid];
    __syncthreads();
    float h = 0.f;
    #pragma unroll
    for (int i = 0; i < 3; i++) {
        float fx = F[b*9 + i*3 + 0]*sp[0] + F[b*9 + i*3 + 1]*sp[1] + F[b*9 + i*3 + 2]*sp[2];
        h = fmaf(fx, W_in[i * 16 + k], h);
    }
    g_h0[n * BHD + tid] = h;
}

// ---------------- one GNN layer: gather-by-dst, scale, @Wl, relu ----------------
__global__ void k_layer(const float* __restrict__ Wl, int layer) {
    const float* __restrict__ hin  = layer ? g_h1 : g_h0;
    float*       __restrict__ hout = layer ? g_h0 : g_h1;
    int n = blockIdx.x, tid = threadIdx.x;
    __shared__ float sW[256], sagg[256], sew[3];
    __shared__ int sedge[128];
    sW[tid] = Wl[tid];
    if (tid < 3) sew[tid] = g_ew[layer * 3 + tid];
    int start = g_rowptr[n], end = g_rowptr[n + 1];
    float acc = 0.f;
    for (int base = start; base < end; base += 128) {
        int cnt = min(128, end - base);
        __syncthreads();
        if (tid < cnt) sedge[tid] = g_csr[base + tid];
        __syncthreads();
        int i = 0;
        for (; i + 8 <= cnt; i += 8) {
            float part = 0.f;
            #pragma unroll
            for (int u = 0; u < 8; u++) {
                int p = sedge[i + u];
                part = fmaf(sew[p >> 16], __ldg(&hin[(p & 0xFFFF) * BHD + tid]), part);
            }
            acc += part;
        }
        for (; i < cnt; i++) {
            int p = sedge[i];
            acc = fmaf(sew[p >> 16], __ldg(&hin[(p & 0xFFFF) * BHD + tid]), acc);
        }
    }
    __syncthreads();
    sagg[tid] = acc * INV_SQRT_DEG;
    __syncthreads();
    int b = tid >> 4, k = tid & 15;
    const float* ar = &sagg[b * 16];
    float s = 0.f;
    #pragma unroll
    for (int kk = 0; kk < 16; kk++) s = fmaf(ar[kk], sW[kk * 16 + k], s);
    hout[n * BHD + tid] = fmaxf(s, 0.f);
}

// ---------------- head: a & c for the first N edges ----------------
__global__ void k_head(const int* __restrict__ edge_src, const int* __restrict__ edge_dst,
                       const float* __restrict__ W_out) {
    int e = blockIdx.x, tid = threadIdx.x;
    __shared__ float sd[256], sa[48];
    int src = edge_src[e], dst = edge_dst[e];
    sd[tid] = g_h0[src * BHD + tid] - g_h0[dst * BHD + tid];
    __syncthreads();
    if (tid < 48) {
        int b = tid / 3, p = tid % 3;
        float a = 0.f;
        #pragma unroll
        for (int k = 0; k < 16; k++) a = fmaf(sd[b * 16 + k], W_out[k * 3 + p], a);
        sa[tid] = a;
        g_A[e * 48 + tid] = a;
    }
    __syncthreads();
    if (tid < 48) {
        int b = tid / 3, q = tid % 3;
        float c = 0.f;
        #pragma unroll
        for (int p = 0; p < 3; p++) c = fmaf(g_invF[b * 9 + q * 3 + p], sa[b * 3 + p], c);
        g_C[e * 48 + tid] = c;
    }
}

// ---------------- R = W2 @ C via packed f32x2 FFMA ----------------
// Block: 256 threads = 32 tr (row lanes) x 8 tc (6-col groups).
// Each thread: 8 rows (tr + 32*m) x 6 cols (tc*6..tc*6+5) packed as f32x2[8][3].
// grid (NN/GROWS=16, KSPLIT=16); each block reduces a 256-wide j range.
__global__ void __launch_bounds__(256) k_gemm(const float* __restrict__ W2) {
    int i0 = blockIdx.x * GROWS;
    int js = blockIdx.y;
    int j0base = js * (NN / KSPLIT);             // 256 j's per split
    __shared__ float Ws[GROWS * WPITCH];         // 256 x 34 = 34.8 KB
    __shared__ __align__(16) float Cs[KJ * 48];  // 6 KB
    int tid = threadIdx.x;
    int tr = tid & 31, tc = tid >> 5;

    unsigned long long acc[8][3];
    #pragma unroll
    for (int m = 0; m < 8; m++)
        #pragma unroll
        for (int u = 0; u < 3; u++) acc[m][u] = 0ull;

    #pragma unroll 1
    for (int jc = 0; jc < (NN / KSPLIT) / KJ; jc++) {   // 8 chunks of 32
        int j0 = j0base + jc * KJ;
        __syncthreads();
        // stage C chunk [KJ x 48] (contiguous in gmem)
        {
            const float4* cg = (const float4*)(g_C + j0 * 48);
            float4* cs = (float4*)Cs;
            for (int t = tid; t < KJ * 12; t += 256) cs[t] = cg[t];
        }
        // stage W2 tile [256 rows x 32 cols], pitch-34 smem
        #pragma unroll
        for (int rep = 0; rep < 8; rep++) {
            int f = rep * 256 + tid;
            int r = f >> 3, c4 = f & 7;
            float4 w = *(const float4*)(W2 + (size_t)(i0 + r) * NN + j0 + c4 * 4);
            float* wd = &Ws[r * WPITCH + c4 * 4];
            wd[0] = w.x; wd[1] = w.y; wd[2] = w.z; wd[3] = w.w;
        }
        __syncthreads();
        #pragma unroll
        for (int jj = 0; jj < KJ; jj += 2) {
            float2 wv[8];
            #pragma unroll
            for (int m = 0; m < 8; m++)
                wv[m] = *(const float2*)&Ws[(tr + 32 * m) * WPITCH + jj];
            const float2* c0 = (const float2*)&Cs[jj * 48 + tc * 6];         // broadcast
            const float2* c1 = (const float2*)&Cs[(jj + 1) * 48 + tc * 6];   // broadcast
            unsigned long long ca0 = ((const unsigned long long*)c0)[0];
            unsigned long long ca1 = ((const unsigned long long*)c0)[1];
            unsigned long long ca2 = ((const unsigned long long*)c0)[2];
            unsigned long long cb0 = ((const unsigned long long*)c1)[0];
            unsigned long long cb1 = ((const unsigned long long*)c1)[1];
            unsigned long long cb2 = ((const unsigned long long*)c1)[2];
            #pragma unroll
            for (int m = 0; m < 8; m++) {
                unsigned long long wlo = pk2(wv[m].x, wv[m].x);
                unsigned long long whi = pk2(wv[m].y, wv[m].y);
                fma2(acc[m][0], wlo, ca0);
                fma2(acc[m][1], wlo, ca1);
                fma2(acc[m][2], wlo, ca2);
                fma2(acc[m][0], whi, cb0);
                fma2(acc[m][1], whi, cb1);
                fma2(acc[m][2], whi, cb2);
            }
        }
    }
    float* out = g_R + (size_t)js * NN * 48;
    #pragma unroll
    for (int m = 0; m < 8; m++) {
        int i = i0 + tr + 32 * m;
        float* op = out + i * 48 + tc * 6;
        #pragma unroll
        for (int u = 0; u < 3; u++) {
            float lo, hi;
            upk2(acc[m][u], lo, hi);
            op[2 * u] = lo; op[2 * u + 1] = hi;
        }
    }
}

// ---------------- stress[b,p,q] = sum_i A[i][b,p] * R[i][b,q] ----------------
__global__ void k_final(float* __restrict__ out) {
    int idx = blockIdx.x;              // 0..143
    int b = idx / 9, r = idx % 9, p = r / 3, q = r % 3;
    int cp = b * 3 + p, cq = b * 3 + q;
    int tid = threadIdx.x;
    float s = 0.f;
    for (int i = tid; i < NN; i += 256) {
        float rv = 0.f;
        #pragma unroll
        for (int sp_ = 0; sp_ < KSPLIT; sp_++)
            rv += g_R[(size_t)sp_ * NN * 48 + i * 48 + cq];
        s = fmaf(g_A[i * 48 + cp], rv, s);
    }
    const unsigned full = 0xFFFFFFFFu;
    #pragma unroll
    for (int off = 16; off > 0; off >>= 1) s += __shfl_down_sync(full, s, off);
    __shared__ float red[8];
    int lane = tid & 31, wid = tid >> 5;
    if (lane == 0) red[wid] = s;
    __syncthreads();
    if (tid == 0) {
        float t = 0.f;
        #pragma unroll
        for (int w = 0; w < 8; w++) t += red[w];
        out[idx] = t;
    }
}

// ---------------- launch ----------------
extern "C" void kernel_launch(void* const* d_in, const int* in_sizes, int n_in,
                              void* d_out, int out_size) {
    const float* F        = (const float*)d_in[0];
    const float* node_pos = (const float*)d_in[1];
    const int*   edge_src = (const int*)d_in[2];
    const int*   edge_dst = (const int*)d_in[3];
    const int*   edge_type= (const int*)d_in[4];
    const float* W_in     = (const float*)d_in[5];
    const float* fc1_0    = (const float*)d_in[6];
    const float* fc2_0    = (const float*)d_in[7];
    const float* W_0      = (const float*)d_in[8];
    const float* fc1_1    = (const float*)d_in[9];
    const float* fc2_1    = (const float*)d_in[10];
    const float* W_1      = (const float*)d_in[11];
    const float* W_out    = (const float*)d_in[12];
    const float* w        = (const float*)d_in[13];
    float* out = (float*)d_out;

    k_init<<<1, 256>>>(F, fc1_0, fc2_0, fc1_1, fc2_1);
    k_hist<<<NE / 256, 256>>>(edge_dst);
    k_scan<<<1, 1024>>>();
    k_scatter<<<NE / 256, 256>>>(edge_src, edge_dst, edge_type);
    k_h0<<<NN, 256>>>(F, node_pos, W_in);
    k_layer<<<NN, 256>>>(W_0, 0);
    k_layer<<<NN, 256>>>(W_1, 1);
    k_head<<<NN, 256>>>(edge_src, edge_dst, W_out);
    k_gemm<<<dim3(NN / GROWS, KSPLIT), 256>>>(w);
    k_final<<<144, 256>>>(out);
}

// round 5
// speedup vs baseline: 1.0225x; 1.0225x over previous
#include <cuda_runtime.h>

#define NB 16
#define NN 4096
#define NE 131072
#define NH 16
#define NT 3
#define NFC 20
#define BHD 256                     // B*H = 256 floats per node row
#define INV_SQRT_DEG 0.17677669529663687f   // 1/sqrt(E/N) = 1/sqrt(32)

#define KSPLIT 16                   // j-reduction splits in k_gemm
#define GROWS 256                   // rows per gemm block
#define KJ 32                       // j-chunk per smem stage
#define WPITCH 34                   // Ws smem pitch (34 mod 32 == 2 -> LDS.64 conflict-free)

// ---------------- device scratch (static: no allocs allowed) ----------------
__device__ __align__(16) float g_h0[NN * BHD];     // final-h buffer (layer1 out)
__device__ __align__(16) float g_h1[NN * BHD];     // layer0 out
__device__ __align__(16) float g_A[NN * 48];       // a[i][b*3+p]
__device__ __align__(16) float g_C[NN * 48];       // c[j][b*3+q]
__device__ __align__(16) float g_R[KSPLIT * NN * 48];   // partial R = W2 @ C
__device__ int   g_cnt[NN];                        // zero-init at load; re-zeroed by k_scan
__device__ int   g_rowptr[NN + 1];
__device__ int   g_cursor[NN];
__device__ int   g_csr[NE];                        // src | (type<<16), sorted by dst
__device__ float g_ew[2 * NT];                     // per-layer per-type edge weight
__device__ float g_invF[NB * 9];
__device__ float g_P[NB * NH * 3];                 // P[b,k,j] = sum_i F[b,i,j] * W_in[i,k]

// ---------------- f32x2 packed-FMA helpers ----------------
__device__ __forceinline__ unsigned long long pk2(float lo, float hi) {
    unsigned long long r;
    asm("mov.b64 %0, {%1, %2};" : "=l"(r) : "f"(lo), "f"(hi));
    return r;
}
__device__ __forceinline__ void upk2(unsigned long long v, float& lo, float& hi) {
    asm("mov.b64 {%0, %1}, %2;" : "=f"(lo), "=f"(hi) : "l"(v));
}
__device__ __forceinline__ void fma2(unsigned long long& d, unsigned long long a,
                                     unsigned long long b) {
    asm("fma.rn.f32x2 %0, %1, %2, %0;" : "+l"(d) : "l"(a), "l"(b));
}

// ---------------- hist (4 edges/thread) + fused one-time init in block 0 ----------------
__global__ void k_hist(const int* __restrict__ edge_dst,
                       const float* __restrict__ F, const float* __restrict__ W_in,
                       const float* __restrict__ fc10, const float* __restrict__ fc20,
                       const float* __restrict__ fc11, const float* __restrict__ fc21) {
    int tid = threadIdx.x;
    int base = blockIdx.x * 1024 + tid;
    #pragma unroll
    for (int u = 0; u < 4; u++) atomicAdd(&g_cnt[edge_dst[base + u * 256]], 1);

    if (blockIdx.x == 0) {
        if (tid < 6) {           // edge weights: relu(onehot@fc1)@fc2 per (layer,type)
            int l = tid / 3, t = tid % 3;
            const float* f1 = l ? fc11 : fc10;
            const float* f2 = l ? fc21 : fc20;
            float s = 0.f;
            #pragma unroll
            for (int f = 0; f < NFC; f++) s = fmaf(fmaxf(f1[t * NFC + f], 0.f), f2[f], s);
            g_ew[tid] = s;
        }
        if (tid >= 32 && tid < 32 + NB) {   // inv(F) per batch
            int b = tid - 32;
            const float* m = F + b * 9;
            float a00=m[0],a01=m[1],a02=m[2],a10=m[3],a11=m[4],a12=m[5],a20=m[6],a21=m[7],a22=m[8];
            float det = a00*(a11*a22-a12*a21) - a01*(a10*a22-a12*a20) + a02*(a10*a21-a11*a20);
            float id = 1.f / det;
            float* o = g_invF + b * 9;
            o[0]=(a11*a22-a12*a21)*id; o[1]=(a02*a21-a01*a22)*id; o[2]=(a01*a12-a02*a11)*id;
            o[3]=(a12*a20-a10*a22)*id; o[4]=(a00*a22-a02*a20)*id; o[5]=(a02*a10-a00*a12)*id;
            o[6]=(a10*a21-a11*a20)*id; o[7]=(a01*a20-a00*a21)*id; o[8]=(a00*a11-a01*a10)*id;
        }
        // P[b,k,j] = sum_i F[b,i,j] * W_in[i,k]   (768 values)
        for (int idx = tid; idx < NB * NH * 3; idx += 256) {
            int b = idx / 48, r = idx % 48, k = r / 3, j = r % 3;
            float s = 0.f;
            #pragma unroll
            for (int i = 0; i < 3; i++) s = fmaf(F[b * 9 + i * 3 + j], W_in[i * 16 + k], s);
            g_P[idx] = s;
        }
    }
}

// ---------------- scan (1 block) + re-zero counters for next replay ----------------
__global__ void k_scan() {
    int tid = threadIdx.x;
    int v[4]; int s = 0;
    #pragma unroll
    for (int j = 0; j < 4; j++) { v[j] = g_cnt[tid * 4 + j]; s += v[j]; }
    #pragma unroll
    for (int j = 0; j < 4; j++) g_cnt[tid * 4 + j] = 0;   // reset for next graph replay
    int lane = tid & 31, wid = tid >> 5;
    const unsigned full = 0xFFFFFFFFu;
    int x = s;
    #pragma unroll
    for (int off = 1; off < 32; off <<= 1) { int y = __shfl_up_sync(full, x, off); if (lane >= off) x += y; }
    __shared__ int swarp[32];
    if (lane == 31) swarp[wid] = x;
    __syncthreads();
    if (wid == 0) {
        int y = swarp[lane];
        #pragma unroll
        for (int off = 1; off < 32; off <<= 1) { int z = __shfl_up_sync(full, y, off); if (lane >= off) y += z; }
        swarp[lane] = y;
    }
    __syncthreads();
    int base = (x - s) + (wid > 0 ? swarp[wid - 1] : 0);
    int run = base;
    #pragma unroll
    for (int j = 0; j < 4; j++) {
        g_rowptr[tid * 4 + j] = run;
        g_cursor[tid * 4 + j] = run;
        run += v[j];
    }
    if (tid == 1023) g_rowptr[NN] = run;
}

__global__ void k_scatter(const int* __restrict__ edge_src,
                          const int* __restrict__ edge_dst,
                          const int* __restrict__ edge_type) {
    int base = blockIdx.x * 1024 + threadIdx.x;
    #pragma unroll
    for (int u = 0; u < 4; u++) {
        int e = base + u * 256;
        int pos = atomicAdd(&g_cursor[edge_dst[e]], 1);
        g_csr[pos] = edge_src[e] | (edge_type[e] << 16);
    }
}

// ---------------- layer 0: h0 computed on the fly from pos (no gather!) ----------------
// h0[src][b,k] = dot(P[b,k,:], pos[src,:]); agg += ew[type] * h0; then @W0, relu.
__global__ void k_layer0(const float* __restrict__ W0, const float* __restrict__ node_pos) {
    int n = blockIdx.x, tid = threadIdx.x;
    __shared__ float sW[256], sagg[256], sew[3];
    __shared__ int sedge[128];
    __shared__ __align__(16) float spos[128 * 4];
    sW[tid] = W0[tid];
    if (tid < 3) sew[tid] = g_ew[tid];
    int b = tid >> 4, k = tid & 15;
    int pi = (b * 16 + k) * 3;
    float p0 = g_P[pi], p1 = g_P[pi + 1], p2 = g_P[pi + 2];
    int start = g_rowptr[n], end = g_rowptr[n + 1];
    float acc = 0.f;
    for (int base = start; base < end; base += 128) {
        int cnt = min(128, end - base);
        __syncthreads();
        if (tid < cnt) {
            int e = g_csr[base + tid];
            sedge[tid] = e;
            int s = e & 0xFFFF;
            spos[tid * 4 + 0] = __ldg(&node_pos[s * 3 + 0]);
            spos[tid * 4 + 1] = __ldg(&node_pos[s * 3 + 1]);
            spos[tid * 4 + 2] = __ldg(&node_pos[s * 3 + 2]);
        }
        __syncthreads();
        for (int u = 0; u < cnt; u++) {
            float4 sp = *(const float4*)&spos[u * 4];      // LDS.128 broadcast
            int e = sedge[u];
            float h0 = fmaf(p2, sp.z, fmaf(p1, sp.y, p0 * sp.x));
            acc = fmaf(sew[e >> 16], h0, acc);
        }
    }
    __syncthreads();
    sagg[tid] = acc * INV_SQRT_DEG;
    __syncthreads();
    const float* ar = &sagg[b * 16];
    float s = 0.f;
    #pragma unroll
    for (int kk = 0; kk < 16; kk++) s = fmaf(ar[kk], sW[kk * 16 + k], s);
    g_h1[n * BHD + tid] = fmaxf(s, 0.f);
}

// ---------------- layer 1: gather h1, scale, @W1, relu -> g_h0 ----------------
__global__ void k_layer1(const float* __restrict__ W1) {
    int n = blockIdx.x, tid = threadIdx.x;
    __shared__ float sW[256], sagg[256], sew[3];
    __shared__ int sedge[128];
    sW[tid] = W1[tid];
    if (tid < 3) sew[tid] = g_ew[3 + tid];
    int start = g_rowptr[n], end = g_rowptr[n + 1];
    float acc = 0.f;
    for (int base = start; base < end; base += 128) {
        int cnt = min(128, end - base);
        __syncthreads();
        if (tid < cnt) sedge[tid] = g_csr[base + tid];
        __syncthreads();
        int i = 0;
        for (; i + 8 <= cnt; i += 8) {
            float part = 0.f;
            #pragma unroll
            for (int u = 0; u < 8; u++) {
                int p = sedge[i + u];
                part = fmaf(sew[p >> 16], __ldg(&g_h1[(p & 0xFFFF) * BHD + tid]), part);
            }
            acc += part;
        }
        for (; i < cnt; i++) {
            int p = sedge[i];
            acc = fmaf(sew[p >> 16], __ldg(&g_h1[(p & 0xFFFF) * BHD + tid]), acc);
        }
    }
    __syncthreads();
    sagg[tid] = acc * INV_SQRT_DEG;
    __syncthreads();
    int b = tid >> 4, k = tid & 15;
    const float* ar = &sagg[b * 16];
    float s = 0.f;
    #pragma unroll
    for (int kk = 0; kk < 16; kk++) s = fmaf(ar[kk], sW[kk * 16 + k], s);
    g_h0[n * BHD + tid] = fmaxf(s, 0.f);
}

// ---------------- head: a & c for the first N edges ----------------
__global__ void k_head(const int* __restrict__ edge_src, const int* __restrict__ edge_dst,
                       const float* __restrict__ W_out) {
    int e = blockIdx.x, tid = threadIdx.x;
    __shared__ float sd[256], sa[48];
    int src = edge_src[e], dst = edge_dst[e];
    sd[tid] = g_h0[src * BHD + tid] - g_h0[dst * BHD + tid];
    __syncthreads();
    if (tid < 48) {
        int b = tid / 3, p = tid % 3;
        float a = 0.f;
        #pragma unroll
        for (int k = 0; k < 16; k++) a = fmaf(sd[b * 16 + k], W_out[k * 3 + p], a);
        sa[tid] = a;
        g_A[e * 48 + tid] = a;
    }
    __syncthreads();
    if (tid < 48) {
        int b = tid / 3, q = tid % 3;
        float c = 0.f;
        #pragma unroll
        for (int p = 0; p < 3; p++) c = fmaf(g_invF[b * 9 + q * 3 + p], sa[b * 3 + p], c);
        g_C[e * 48 + tid] = c;
    }
}

// ---------------- R = W2 @ C via packed f32x2 FFMA ----------------
__global__ void __launch_bounds__(256) k_gemm(const float* __restrict__ W2) {
    int i0 = blockIdx.x * GROWS;
    int js = blockIdx.y;
    int j0base = js * (NN / KSPLIT);             // 256 j's per split
    __shared__ float Ws[GROWS * WPITCH];         // 256 x 34 = 34.8 KB
    __shared__ __align__(16) float Cs[KJ * 48];  // 6 KB
    int tid = threadIdx.x;
    int tr = tid & 31, tc = tid >> 5;

    unsigned long long acc[8][3];
    #pragma unroll
    for (int m = 0; m < 8; m++)
        #pragma unroll
        for (int u = 0; u < 3; u++) acc[m][u] = 0ull;

    #pragma unroll 1
    for (int jc = 0; jc < (NN / KSPLIT) / KJ; jc++) {   // 8 chunks of 32
        int j0 = j0base + jc * KJ;
        __syncthreads();
        {
            const float4* cg = (const float4*)(g_C + j0 * 48);
            float4* cs = (float4*)Cs;
            for (int t = tid; t < KJ * 12; t += 256) cs[t] = cg[t];
        }
        #pragma unroll
        for (int rep = 0; rep < 8; rep++) {
            int f = rep * 256 + tid;
            int r = f >> 3, c4 = f & 7;
            float4 w = *(const float4*)(W2 + (size_t)(i0 + r) * NN + j0 + c4 * 4);
            float* wd = &Ws[r * WPITCH + c4 * 4];
            wd[0] = w.x; wd[1] = w.y; wd[2] = w.z; wd[3] = w.w;
        }
        __syncthreads();
        #pragma unroll
        for (int jj = 0; jj < KJ; jj += 2) {
            float2 wv[8];
            #pragma unroll
            for (int m = 0; m < 8; m++)
                wv[m] = *(const float2*)&Ws[(tr + 32 * m) * WPITCH + jj];
            const float2* c0 = (const float2*)&Cs[jj * 48 + tc * 6];
            const float2* c1 = (const float2*)&Cs[(jj + 1) * 48 + tc * 6];
            unsigned long long ca0 = ((const unsigned long long*)c0)[0];
            unsigned long long ca1 = ((const unsigned long long*)c0)[1];
            unsigned long long ca2 = ((const unsigned long long*)c0)[2];
            unsigned long long cb0 = ((const unsigned long long*)c1)[0];
            unsigned long long cb1 = ((const unsigned long long*)c1)[1];
            unsigned long long cb2 = ((const unsigned long long*)c1)[2];
            #pragma unroll
            for (int m = 0; m < 8; m++) {
                unsigned long long wlo = pk2(wv[m].x, wv[m].x);
                unsigned long long whi = pk2(wv[m].y, wv[m].y);
                fma2(acc[m][0], wlo, ca0);
                fma2(acc[m][1], wlo, ca1);
                fma2(acc[m][2], wlo, ca2);
                fma2(acc[m][0], whi, cb0);
                fma2(acc[m][1], whi, cb1);
                fma2(acc[m][2], whi, cb2);
            }
        }
    }
    float* out = g_R + (size_t)js * NN * 48;
    #pragma unroll
    for (int m = 0; m < 8; m++) {
        int i = i0 + tr + 32 * m;
        float* op = out + i * 48 + tc * 6;
        #pragma unroll
        for (int u = 0; u < 3; u++) {
            float lo, hi;
            upk2(acc[m][u], lo, hi);
            op[2 * u] = lo; op[2 * u + 1] = hi;
        }
    }
}

// ---------------- stress[b,p,q] = sum_i A[i][b,p] * R[i][b,q] ----------------
__global__ void k_final(float* __restrict__ out) {
    int idx = blockIdx.x;              // 0..143
    int b = idx / 9, r = idx % 9, p = r / 3, q = r % 3;
    int cp = b * 3 + p, cq = b * 3 + q;
    int tid = threadIdx.x;
    float s = 0.f;
    for (int i = tid; i < NN; i += 256) {
        float rv = 0.f;
        #pragma unroll
        for (int sp_ = 0; sp_ < KSPLIT; sp_++)
            rv += g_R[(size_t)sp_ * NN * 48 + i * 48 + cq];
        s = fmaf(g_A[i * 48 + cp], rv, s);
    }
    const unsigned full = 0xFFFFFFFFu;
    #pragma unroll
    for (int off = 16; off > 0; off >>= 1) s += __shfl_down_sync(full, s, off);
    __shared__ float red[8];
    int lane = tid & 31, wid = tid >> 5;
    if (lane == 0) red[wid] = s;
    __syncthreads();
    if (tid == 0) {
        float t = 0.f;
        #pragma unroll
        for (int w = 0; w < 8; w++) t += red[w];
        out[idx] = t;
    }
}

// ---------------- launch ----------------
extern "C" void kernel_launch(void* const* d_in, const int* in_sizes, int n_in,
                              void* d_out, int out_size) {
    const float* F        = (const float*)d_in[0];
    const float* node_pos = (const float*)d_in[1];
    const int*   edge_src = (const int*)d_in[2];
    const int*   edge_dst = (const int*)d_in[3];
    const int*   edge_type= (const int*)d_in[4];
    const float* W_in     = (const float*)d_in[5];
    const float* fc1_0    = (const float*)d_in[6];
    const float* fc2_0    = (const float*)d_in[7];
    const float* W_0      = (const float*)d_in[8];
    const float* fc1_1    = (const float*)d_in[9];
    const float* fc2_1    = (const float*)d_in[10];
    const float* W_1      = (const float*)d_in[11];
    const float* W_out    = (const float*)d_in[12];
    const float* w        = (const float*)d_in[13];
    float* out = (float*)d_out;

    k_hist<<<NE / 1024, 256>>>(edge_dst, F, W_in, fc1_0, fc2_0, fc1_1, fc2_1);
    k_scan<<<1, 1024>>>();
    k_scatter<<<NE / 1024, 256>>>(edge_src, edge_dst, edge_type);
    k_layer0<<<NN, 256>>>(W_0, node_pos);
    k_layer1<<<NN, 256>>>(W_1);
    k_head<<<NN, 256>>>(edge_src, edge_dst, W_out);
    k_gemm<<<dim3(NN / GROWS, KSPLIT), 256>>>(w);
    k_final<<<144, 256>>>(out);
}

// round 6
// speedup vs baseline: 1.0638x; 1.0404x over previous
#include <cuda_runtime.h>

#define NB 16
#define NN 4096
#define NE 131072
#define NH 16
#define NT 3
#define NFC 20
#define BHD 256                     // B*H = 256 floats per node row
#define INV_SQRT_DEG 0.17677669529663687f   // 1/sqrt(E/N) = 1/sqrt(32)

#define KSPLIT 16                   // j-reduction splits in k_gemm
#define GROWS 256                   // rows per gemm block
#define KJ 32                       // j-chunk per smem stage
#define WPITCH 34                   // Ws smem pitch (34 mod 32 == 2 -> LDS.64 conflict-free)

// ---------------- device scratch (static: no allocs allowed) ----------------
__device__ __align__(16) float g_h0[NN * BHD];     // final-h buffer (layer1 out)
__device__ __align__(16) float g_h1[NN * BHD];     // layer0 out
__device__ __align__(16) float g_A[NN * 48];       // a[i][b*3+p]
__device__ __align__(16) float g_C[NN * 48];       // c[j][b*3+q]
__device__ __align__(16) float g_R[KSPLIT * NN * 48];   // partial R = W2 @ C
__device__ int   g_cnt[NN];                        // zero-init; re-zeroed by k_scan
__device__ int   g_rowptr[NN + 1];
__device__ int   g_cursor[NN];
__device__ int   g_csr[NE];                        // src | (type<<16), sorted by dst
__device__ float g_ew[2 * NT];                     // per-layer per-type edge weight
__device__ float g_invF[NB * 9];
__device__ float g_P[NB * NH * 3];                 // P[b,k,j] = sum_i F[b,i,j] * W_in[i,k]
__device__ float g_S[NN * 3];                      // S[n,j] = sum_{e->n} ew0[t]*pos[src,j]
                                                   // zero-init; re-zeroed by k_scan

// ---------------- f32x2 packed-FMA helpers ----------------
__device__ __forceinline__ unsigned long long pk2(float lo, float hi) {
    unsigned long long r;
    asm("mov.b64 %0, {%1, %2};" : "=l"(r) : "f"(lo), "f"(hi));
    return r;
}
__device__ __forceinline__ void upk2(unsigned long long v, float& lo, float& hi) {
    asm("mov.b64 {%0, %1}, %2;" : "=f"(lo), "=f"(hi) : "l"(v));
}
__device__ __forceinline__ void fma2(unsigned long long& d, unsigned long long a,
                                     unsigned long long b) {
    asm("fma.rn.f32x2 %0, %1, %2, %0;" : "+l"(d) : "l"(a), "l"(b));
}

// ---------------- hist (4 edges/thread) + fused one-time init in block 0 ----------------
__global__ void k_hist(const int* __restrict__ edge_dst,
                       const float* __restrict__ F, const float* __restrict__ W_in,
                       const float* __restrict__ fc10, const float* __restrict__ fc20,
                       const float* __restrict__ fc11, const float* __restrict__ fc21) {
    int tid = threadIdx.x;
    int base = blockIdx.x * 1024 + tid;
    #pragma unroll
    for (int u = 0; u < 4; u++) atomicAdd(&g_cnt[edge_dst[base + u * 256]], 1);

    if (blockIdx.x == 0) {
        if (tid < 6) {           // edge weights: relu(onehot@fc1)@fc2 per (layer,type)
            int l = tid / 3, t = tid % 3;
            const float* f1 = l ? fc11 : fc10;
            const float* f2 = l ? fc21 : fc20;
            float s = 0.f;
            #pragma unroll
            for (int f = 0; f < NFC; f++) s = fmaf(fmaxf(f1[t * NFC + f], 0.f), f2[f], s);
            g_ew[tid] = s;
        }
        if (tid >= 32 && tid < 32 + NB) {   // inv(F) per batch
            int b = tid - 32;
            const float* m = F + b * 9;
            float a00=m[0],a01=m[1],a02=m[2],a10=m[3],a11=m[4],a12=m[5],a20=m[6],a21=m[7],a22=m[8];
            float det = a00*(a11*a22-a12*a21) - a01*(a10*a22-a12*a20) + a02*(a10*a21-a11*a20);
            float id = 1.f / det;
            float* o = g_invF + b * 9;
            o[0]=(a11*a22-a12*a21)*id; o[1]=(a02*a21-a01*a22)*id; o[2]=(a01*a12-a02*a11)*id;
            o[3]=(a12*a20-a10*a22)*id; o[4]=(a00*a22-a02*a20)*id; o[5]=(a02*a10-a00*a12)*id;
            o[6]=(a10*a21-a11*a20)*id; o[7]=(a01*a20-a00*a21)*id; o[8]=(a00*a11-a01*a10)*id;
        }
        // P[b,k,j] = sum_i F[b,i,j] * W_in[i,k]   (768 values)
        for (int idx = tid; idx < NB * NH * 3; idx += 256) {
            int b = idx / 48, r = idx % 48, k = r / 3, j = r % 3;
            float s = 0.f;
            #pragma unroll
            for (int i = 0; i < 3; i++) s = fmaf(F[b * 9 + i * 3 + j], W_in[i * 16 + k], s);
            g_P[idx] = s;
        }
    }
}

// ---------------- scan (1 block) + re-zero cnt + zero S for scatter ----------------
__global__ void k_scan() {
    int tid = threadIdx.x;
    #pragma unroll
    for (int j = 0; j < 12; j++) {
        int idx = tid * 12 + j;
        if (idx < NN * 3) g_S[idx] = 0.f;
    }
    int v[4]; int s = 0;
    #pragma unroll
    for (int j = 0; j < 4; j++) { v[j] = g_cnt[tid * 4 + j]; s += v[j]; }
    #pragma unroll
    for (int j = 0; j < 4; j++) g_cnt[tid * 4 + j] = 0;   // reset for next graph replay
    int lane = tid & 31, wid = tid >> 5;
    const unsigned full = 0xFFFFFFFFu;
    int x = s;
    #pragma unroll
    for (int off = 1; off < 32; off <<= 1) { int y = __shfl_up_sync(full, x, off); if (lane >= off) x += y; }
    __shared__ int swarp[32];
    if (lane == 31) swarp[wid] = x;
    __syncthreads();
    if (wid == 0) {
        int y = swarp[lane];
        #pragma unroll
        for (int off = 1; off < 32; off <<= 1) { int z = __shfl_up_sync(full, y, off); if (lane >= off) y += z; }
        swarp[lane] = y;
    }
    __syncthreads();
    int base = (x - s) + (wid > 0 ? swarp[wid - 1] : 0);
    int run = base;
    #pragma unroll
    for (int j = 0; j < 4; j++) {
        g_rowptr[tid * 4 + j] = run;
        g_cursor[tid * 4 + j] = run;
        run += v[j];
    }
    if (tid == 1023) g_rowptr[NN] = run;
}

// ---------------- scatter: build CSR + accumulate S = sum ew0[t]*pos[src] ----------------
__global__ void k_scatter(const int* __restrict__ edge_src,
                          const int* __restrict__ edge_dst,
                          const int* __restrict__ edge_type,
                          const float* __restrict__ node_pos) {
    int base = blockIdx.x * 1024 + threadIdx.x;
    #pragma unroll
    for (int u = 0; u < 4; u++) {
        int e = base + u * 256;
        int s = edge_src[e], d = edge_dst[e], t = edge_type[e];
        int pos = atomicAdd(&g_cursor[d], 1);
        g_csr[pos] = s | (t << 16);
        float w = g_ew[t];
        atomicAdd(&g_S[d * 3 + 0], w * __ldg(&node_pos[s * 3 + 0]));
        atomicAdd(&g_S[d * 3 + 1], w * __ldg(&node_pos[s * 3 + 1]));
        atomicAdd(&g_S[d * 3 + 2], w * __ldg(&node_pos[s * 3 + 2]));
    }
}

// ---------------- layer 0 (closed form): agg = dot(P[b,k], S[n]); @W0, relu ----------------
__global__ void k_layer0(const float* __restrict__ W0) {
    int n = blockIdx.x, tid = threadIdx.x;
    __shared__ float sW[256], sagg[256];
    sW[tid] = W0[tid];
    float s0 = g_S[n * 3 + 0], s1 = g_S[n * 3 + 1], s2 = g_S[n * 3 + 2];
    int pi = tid * 3;   // (b*16+k)*3 == tid*3
    float acc = fmaf(g_P[pi + 2], s2, fmaf(g_P[pi + 1], s1, g_P[pi] * s0));
    sagg[tid] = acc * INV_SQRT_DEG;
    __syncthreads();
    int b = tid >> 4, k = tid & 15;
    const float* ar = &sagg[b * 16];
    float s = 0.f;
    #pragma unroll
    for (int kk = 0; kk < 16; kk++) s = fmaf(ar[kk], sW[kk * 16 + k], s);
    g_h1[n * BHD + tid] = fmaxf(s, 0.f);
}

// ---------------- layer 1: gather h1, scale, @W1, relu -> g_h0 ----------------
__global__ void k_layer1(const float* __restrict__ W1) {
    int n = blockIdx.x, tid = threadIdx.x;
    __shared__ float sW[256], sagg[256], sew[3];
    __shared__ int sedge[128];
    sW[tid] = W1[tid];
    if (tid < 3) sew[tid] = g_ew[3 + tid];
    int start = g_rowptr[n], end = g_rowptr[n + 1];
    float acc = 0.f;
    for (int base = start; base < end; base += 128) {
        int cnt = min(128, end - base);
        __syncthreads();
        if (tid < cnt) sedge[tid] = g_csr[base + tid];
        __syncthreads();
        int i = 0;
        for (; i + 8 <= cnt; i += 8) {
            float part = 0.f;
            #pragma unroll
            for (int u = 0; u < 8; u++) {
                int p = sedge[i + u];
                part = fmaf(sew[p >> 16], __ldg(&g_h1[(p & 0xFFFF) * BHD + tid]), part);
            }
            acc += part;
        }
        for (; i < cnt; i++) {
            int p = sedge[i];
            acc = fmaf(sew[p >> 16], __ldg(&g_h1[(p & 0xFFFF) * BHD + tid]), acc);
        }
    }
    __syncthreads();
    sagg[tid] = acc * INV_SQRT_DEG;
    __syncthreads();
    int b = tid >> 4, k = tid & 15;
    const float* ar = &sagg[b * 16];
    float s = 0.f;
    #pragma unroll
    for (int kk = 0; kk < 16; kk++) s = fmaf(ar[kk], sW[kk * 16 + k], s);
    g_h0[n * BHD + tid] = fmaxf(s, 0.f);
}

// ---------------- head: a & c for the first N edges ----------------
__global__ void k_head(const int* __restrict__ edge_src, const int* __restrict__ edge_dst,
                       const float* __restrict__ W_out) {
    int e = blockIdx.x, tid = threadIdx.x;
    __shared__ float sd[256], sa[48];
    int src = edge_src[e], dst = edge_dst[e];
    sd[tid] = g_h0[src * BHD + tid] - g_h0[dst * BHD + tid];
    __syncthreads();
    if (tid < 48) {
        int b = tid / 3, p = tid % 3;
        float a = 0.f;
        #pragma unroll
        for (int k = 0; k < 16; k++) a = fmaf(sd[b * 16 + k], W_out[k * 3 + p], a);
        sa[tid] = a;
        g_A[e * 48 + tid] = a;
    }
    __syncthreads();
    if (tid < 48) {
        int b = tid / 3, q = tid % 3;
        float c = 0.f;
        #pragma unroll
        for (int p = 0; p < 3; p++) c = fmaf(g_invF[b * 9 + q * 3 + p], sa[b * 3 + p], c);
        g_C[e * 48 + tid] = c;
    }
}

// ---------------- R = W2 @ C via packed f32x2 FFMA ----------------
__global__ void __launch_bounds__(256) k_gemm(const float* __restrict__ W2) {
    int i0 = blockIdx.x * GROWS;
    int js = blockIdx.y;
    int j0base = js * (NN / KSPLIT);             // 256 j's per split
    __shared__ float Ws[GROWS * WPITCH];         // 256 x 34 = 34.8 KB
    __shared__ __align__(16) float Cs[KJ * 48];  // 6 KB
    int tid = threadIdx.x;
    int tr = tid & 31, tc = tid >> 5;

    unsigned long long acc[8][3];
    #pragma unroll
    for (int m = 0; m < 8; m++)
        #pragma unroll
        for (int u = 0; u < 3; u++) acc[m][u] = 0ull;

    #pragma unroll 1
    for (int jc = 0; jc < (NN / KSPLIT) / KJ; jc++) {   // 8 chunks of 32
        int j0 = j0base + jc * KJ;
        __syncthreads();
        {
            const float4* cg = (const float4*)(g_C + j0 * 48);
            float4* cs = (float4*)Cs;
            for (int t = tid; t < KJ * 12; t += 256) cs[t] = cg[t];
        }
        #pragma unroll
        for (int rep = 0; rep < 8; rep++) {
            int f = rep * 256 + tid;
            int r = f >> 3, c4 = f & 7;
            float4 w = *(const float4*)(W2 + (size_t)(i0 + r) * NN + j0 + c4 * 4);
            float* wd = &Ws[r * WPITCH + c4 * 4];
            wd[0] = w.x; wd[1] = w.y; wd[2] = w.z; wd[3] = w.w;
        }
        __syncthreads();
        #pragma unroll
        for (int jj = 0; jj < KJ; jj += 2) {
            float2 wv[8];
            #pragma unroll
            for (int m = 0; m < 8; m++)
                wv[m] = *(const float2*)&Ws[(tr + 32 * m) * WPITCH + jj];
            const float2* c0 = (const float2*)&Cs[jj * 48 + tc * 6];
            const float2* c1 = (const float2*)&Cs[(jj + 1) * 48 + tc * 6];
            unsigned long long ca0 = ((const unsigned long long*)c0)[0];
            unsigned long long ca1 = ((const unsigned long long*)c0)[1];
            unsigned long long ca2 = ((const unsigned long long*)c0)[2];
            unsigned long long cb0 = ((const unsigned long long*)c1)[0];
            unsigned long long cb1 = ((const unsigned long long*)c1)[1];
            unsigned long long cb2 = ((const unsigned long long*)c1)[2];
            #pragma unroll
            for (int m = 0; m < 8; m++) {
                unsigned long long wlo = pk2(wv[m].x, wv[m].x);
                unsigned long long whi = pk2(wv[m].y, wv[m].y);
                fma2(acc[m][0], wlo, ca0);
                fma2(acc[m][1], wlo, ca1);
                fma2(acc[m][2], wlo, ca2);
                fma2(acc[m][0], whi, cb0);
                fma2(acc[m][1], whi, cb1);
                fma2(acc[m][2], whi, cb2);
            }
        }
    }
    float* out = g_R + (size_t)js * NN * 48;
    #pragma unroll
    for (int m = 0; m < 8; m++) {
        int i = i0 + tr + 32 * m;
        float* op = out + i * 48 + tc * 6;
        #pragma unroll
        for (int u = 0; u < 3; u++) {
            float lo, hi;
            upk2(acc[m][u], lo, hi);
            op[2 * u] = lo; op[2 * u + 1] = hi;
        }
    }
}

// ---------------- stress[b,p,q] = sum_i A[i][b,p] * R[i][b,q] ----------------
__global__ void k_final(float* __restrict__ out) {
    int idx = blockIdx.x;              // 0..143
    int b = idx / 9, r = idx % 9, p = r / 3, q = r % 3;
    int cp = b * 3 + p, cq = b * 3 + q;
    int tid = threadIdx.x;
    float s = 0.f;
    for (int i = tid; i < NN; i += 256) {
        float rv = 0.f;
        #pragma unroll
        for (int sp_ = 0; sp_ < KSPLIT; sp_++)
            rv += g_R[(size_t)sp_ * NN * 48 + i * 48 + cq];
        s = fmaf(g_A[i * 48 + cp], rv, s);
    }
    const unsigned full = 0xFFFFFFFFu;
    #pragma unroll
    for (int off = 16; off > 0; off >>= 1) s += __shfl_down_sync(full, s, off);
    __shared__ float red[8];
    int lane = tid & 31, wid = tid >> 5;
    if (lane == 0) red[wid] = s;
    __syncthreads();
    if (tid == 0) {
        float t = 0.f;
        #pragma unroll
        for (int w = 0; w < 8; w++) t += red[w];
        out[idx] = t;
    }
}

// ---------------- launch ----------------
extern "C" void kernel_launch(void* const* d_in, const int* in_sizes, int n_in,
                              void* d_out, int out_size) {
    const float* F        = (const float*)d_in[0];
    const float* node_pos = (const float*)d_in[1];
    const int*   edge_src = (const int*)d_in[2];
    const int*   edge_dst = (const int*)d_in[3];
    const int*   edge_type= (const int*)d_in[4];
    const float* W_in     = (const float*)d_in[5];
    const float* fc1_0    = (const float*)d_in[6];
    const float* fc2_0    = (const float*)d_in[7];
    const float* W_0      = (const float*)d_in[8];
    const float* fc1_1    = (const float*)d_in[9];
    const float* fc2_1    = (const float*)d_in[10];
    const float* W_1      = (const float*)d_in[11];
    const float* W_out    = (const float*)d_in[12];
    const float* w        = (const float*)d_in[13];
    float* out = (float*)d_out;

    k_hist<<<NE / 1024, 256>>>(edge_dst, F, W_in, fc1_0, fc2_0, fc1_1, fc2_1);
    k_scan<<<1, 1024>>>();
    k_scatter<<<NE / 1024, 256>>>(edge_src, edge_dst, edge_type, node_pos);
    k_layer0<<<NN, 256>>>(W_0);
    k_layer1<<<NN, 256>>>(W_1);
    k_head<<<NN, 256>>>(edge_src, edge_dst, W_out);
    k_gemm<<<dim3(NN / GROWS, KSPLIT), 256>>>(w);
    k_final<<<144, 256>>>(out);
}